// round 1
// baseline (speedup 1.0000x reference)
#include <cuda_runtime.h>
#include <stdint.h>

// Problem dims (fixed by the dataset)
#define TOKENS 256
#define IN_F   4096
#define OUT_F  11008
#define RANK   16
#define SCALING 2.0f   // 32/16

// Tiling
#define BM 64
#define BN 64
#define BK 16
#define TM 8
#define TN 4
#define THREADS 128   // (BM/TM)*(BN/TN) = 8*16

__constant__ float c_nf4[16] = {
    -1.0f, -0.6961928009986877f, -0.5250730514526367f, -0.39491748809814453f,
    -0.28444138169288635f, -0.18477343022823334f, -0.09105003625154495f, 0.0f,
    0.07958029955625534f, 0.16093020141124725f, 0.24611230194568634f,
    0.33791524171829224f, 0.44070982933044434f, 0.5626170039176941f,
    0.7229568362236023f, 1.0f
};

// LoRA intermediate u[t][r] = SCALING * sum_k x[t][k] * A[r][k]
__device__ float g_u[TOKENS * RANK];

__global__ void lora_u_kernel(const float* __restrict__ x,
                              const float* __restrict__ A) {
    const int t   = blockIdx.x;       // token
    const int tid = threadIdx.x;      // 256 threads

    float acc[RANK];
#pragma unroll
    for (int r = 0; r < RANK; r++) acc[r] = 0.0f;

    const float* xr = x + (size_t)t * IN_F;
    for (int k = tid; k < IN_F; k += 256) {
        float xv = xr[k];
#pragma unroll
        for (int r = 0; r < RANK; r++)
            acc[r] += xv * A[r * IN_F + k];
    }

    __shared__ float red[RANK];
    if (tid < RANK) red[tid] = 0.0f;
    __syncthreads();

#pragma unroll
    for (int r = 0; r < RANK; r++) {
        float v = acc[r];
#pragma unroll
        for (int off = 16; off > 0; off >>= 1)
            v += __shfl_down_sync(0xFFFFFFFFu, v, off);
        if ((tid & 31) == 0) atomicAdd(&red[r], v);
    }
    __syncthreads();
    if (tid < RANK) g_u[t * RANK + tid] = red[tid] * SCALING;
}

__global__ __launch_bounds__(THREADS)
void lora4bit_main_kernel(const float* __restrict__ x,
                          const int*   __restrict__ q,
                          const float* __restrict__ absmax,
                          const float* __restrict__ lora_B,
                          float*       __restrict__ out) {
    __shared__ float xs[BK][BM + 1];
    __shared__ float ws[BK][BN + 1];
    __shared__ float lut[16];

    const int tid = threadIdx.x;
    if (tid < 16) lut[tid] = c_nf4[tid];

    const int bn = blockIdx.x * BN;   // out_f offset (172 blocks)
    const int bm = blockIdx.y * BM;   // token offset (4 blocks)

    const int tn = (tid & 15) * TN;   // 16 threads in n
    const int tm = (tid >> 4) * TM;   // 8 threads in m

    float acc[TM][TN];
#pragma unroll
    for (int i = 0; i < TM; i++)
#pragma unroll
        for (int j = 0; j < TN; j++) acc[i][j] = 0.0f;

    // Loader mapping: each thread loads 16 contiguous k-elems of one row,
    // split into two 16B vectors.
    const int lr = tid >> 1;            // row in tile, 0..63
    const int lc = (tid & 1) * 8;       // k offset within tile: 0 or 8

    const float* xg_base = x + (size_t)(bm + lr) * IN_F + lc;
    const int*   qg_base = q + (size_t)(bn + lr) * IN_F + lc;
    const float* am_base = absmax + (size_t)(bn + lr) * (IN_F / 64);

    for (int k0 = 0; k0 < IN_F; k0 += BK) {
        // Global loads for this tile (issued before the sync for overlap)
        const float4* xg = (const float4*)(xg_base + k0);
        float4 xa = xg[0];
        float4 xb = xg[1];
        const int4* qg = (const int4*)(qg_base + k0);
        int4 qa = qg[0];
        int4 qb = qg[1];
        float scale = am_base[k0 >> 6];

        __syncthreads();   // previous-iteration consumers done

        xs[lc + 0][lr] = xa.x; xs[lc + 1][lr] = xa.y;
        xs[lc + 2][lr] = xa.z; xs[lc + 3][lr] = xa.w;
        xs[lc + 4][lr] = xb.x; xs[lc + 5][lr] = xb.y;
        xs[lc + 6][lr] = xb.z; xs[lc + 7][lr] = xb.w;

        ws[lc + 0][lr] = lut[qa.x & 15] * scale;
        ws[lc + 1][lr] = lut[qa.y & 15] * scale;
        ws[lc + 2][lr] = lut[qa.z & 15] * scale;
        ws[lc + 3][lr] = lut[qa.w & 15] * scale;
        ws[lc + 4][lr] = lut[qb.x & 15] * scale;
        ws[lc + 5][lr] = lut[qb.y & 15] * scale;
        ws[lc + 6][lr] = lut[qb.z & 15] * scale;
        ws[lc + 7][lr] = lut[qb.w & 15] * scale;

        __syncthreads();

#pragma unroll
        for (int k = 0; k < BK; k++) {
            float a[TM], b[TN];
#pragma unroll
            for (int i = 0; i < TM; i++) a[i] = xs[k][tm + i];
#pragma unroll
            for (int j = 0; j < TN; j++) b[j] = ws[k][tn + j];
#pragma unroll
            for (int i = 0; i < TM; i++)
#pragma unroll
                for (int j = 0; j < TN; j++)
                    acc[i][j] += a[i] * b[j];
        }
    }

    // LoRA epilogue: acc += u[m][r] * B[o][r]
#pragma unroll
    for (int r = 0; r < RANK; r++) {
        float b[TN];
#pragma unroll
        for (int j = 0; j < TN; j++)
            b[j] = lora_B[(size_t)(bn + tn + j) * RANK + r];
#pragma unroll
        for (int i = 0; i < TM; i++) {
            float uv = g_u[(bm + tm + i) * RANK + r];
#pragma unroll
            for (int j = 0; j < TN; j++)
                acc[i][j] += uv * b[j];
        }
    }

    // Write out (TN=4 contiguous floats -> float4)
#pragma unroll
    for (int i = 0; i < TM; i++) {
        float4 v = make_float4(acc[i][0], acc[i][1], acc[i][2], acc[i][3]);
        *(float4*)(out + (size_t)(bm + tm + i) * OUT_F + bn + tn) = v;
    }
}

extern "C" void kernel_launch(void* const* d_in, const int* in_sizes, int n_in,
                              void* d_out, int out_size) {
    const float* x      = (const float*)d_in[0];
    const int*   q      = (const int*)  d_in[1];
    const float* absmax = (const float*)d_in[2];
    const float* lora_A = (const float*)d_in[3];
    const float* lora_B = (const float*)d_in[4];
    float* out = (float*)d_out;

    lora_u_kernel<<<TOKENS, 256>>>(x, lora_A);

    dim3 grid(OUT_F / BN, TOKENS / BM);   // (172, 4)
    lora4bit_main_kernel<<<grid, THREADS>>>(x, q, absmax, lora_B, out);
}

// round 4
// speedup vs baseline: 2.5691x; 2.5691x over previous
#include <cuda_runtime.h>
#include <cuda_bf16.h>
#include <stdint.h>

#define TOKENS 256
#define IN_F   4096
#define OUT_F  11008
#define RANK   16
#define SCALINGF 2.0f

#define BM 128
#define BN 64
#define BK 64
#define THREADS 128
#define K_ITERS (IN_F / BK)   // 64

// per-stage byte offsets within the (1024-aligned) dynamic smem region
#define XHI_OFF 0
#define XLO_OFF 16384
#define WHI_OFF 32768
#define WLO_OFF 40960
#define STAGE_BYTES 49152
#define SMEM_DYN (2 * STAGE_BYTES + 1024)   // +1024 alignment slack

__constant__ float c_nf4[16] = {
    -1.0f, -0.6961928009986877f, -0.5250730514526367f, -0.39491748809814453f,
    -0.28444138169288635f, -0.18477343022823334f, -0.09105003625154495f, 0.0f,
    0.07958029955625534f, 0.16093020141124725f, 0.24611230194568634f,
    0.33791524171829224f, 0.44070982933044434f, 0.5626170039176941f,
    0.7229568362236023f, 1.0f
};

__device__ float g_u[TOKENS * RANK];
__device__ __align__(16) __nv_bfloat16 g_xhi[TOKENS * IN_F];
__device__ __align__(16) __nv_bfloat16 g_xlo[TOKENS * IN_F];

// ------------------------------------------------------------------ helpers
__device__ __forceinline__ uint32_t smem_u32(const void* p) {
    uint32_t a;
    asm("{ .reg .u64 t; cvta.to.shared.u64 t, %1; cvt.u32.u64 %0, t; }"
        : "=r"(a) : "l"(p));
    return a;
}

__device__ __forceinline__ uint32_t sw128(uint32_t o) {
    return o ^ ((o >> 3) & 0x70);
}

__device__ __forceinline__ void cp16(uint32_t dst, const void* src) {
    asm volatile("cp.async.cg.shared.global [%0], [%1], 16;"
                 :: "r"(dst), "l"(src) : "memory");
}
__device__ __forceinline__ void cp_commit() {
    asm volatile("cp.async.commit_group;" ::: "memory");
}
__device__ __forceinline__ void cp_wait0() {
    asm volatile("cp.async.wait_group 0;" ::: "memory");
}

__device__ __forceinline__ void ldsm4(uint32_t* r, uint32_t addr) {
    asm volatile("ldmatrix.sync.aligned.m8n8.x4.shared.b16 {%0,%1,%2,%3}, [%4];"
                 : "=r"(r[0]), "=r"(r[1]), "=r"(r[2]), "=r"(r[3]) : "r"(addr));
}

__device__ __forceinline__ void mma16816(float* c, const uint32_t* a,
                                         const uint32_t* b) {
    asm volatile(
        "mma.sync.aligned.m16n8k16.row.col.f32.bf16.bf16.f32 "
        "{%0,%1,%2,%3},{%4,%5,%6,%7},{%8,%9},{%0,%1,%2,%3};"
        : "+f"(c[0]), "+f"(c[1]), "+f"(c[2]), "+f"(c[3])
        : "r"(a[0]), "r"(a[1]), "r"(a[2]), "r"(a[3]), "r"(b[0]), "r"(b[1]));
}

__device__ __forceinline__ float dot16(const float* a, const float* b) {
    float s = 0.0f;
#pragma unroll
    for (int v = 0; v < 4; ++v) {
        float4 x = ((const float4*)a)[v];
        float4 y = ((const float4*)b)[v];
        s += x.x * y.x + x.y * y.y + x.z * y.z + x.w * y.w;
    }
    return s;
}

// ------------------------------------------------------------------ prep
__global__ void prep_kernel(const float* __restrict__ x,
                            const float* __restrict__ A) {
    const int t = blockIdx.x;
    const int tid = threadIdx.x;

    float acc[RANK];
#pragma unroll
    for (int r = 0; r < RANK; r++) acc[r] = 0.0f;

    const float* xr = x + (size_t)t * IN_F;
    for (int k = tid; k < IN_F; k += 256) {
        float xv = xr[k];
        __nv_bfloat16 hi = __float2bfloat16(xv);
        g_xhi[t * IN_F + k] = hi;
        g_xlo[t * IN_F + k] = __float2bfloat16(xv - __bfloat162float(hi));
#pragma unroll
        for (int r = 0; r < RANK; r++)
            acc[r] += xv * A[r * IN_F + k];
    }

    __shared__ float red[RANK];
    if (tid < RANK) red[tid] = 0.0f;
    __syncthreads();
#pragma unroll
    for (int r = 0; r < RANK; r++) {
        float v = acc[r];
#pragma unroll
        for (int off = 16; off > 0; off >>= 1)
            v += __shfl_down_sync(0xFFFFFFFFu, v, off);
        if ((tid & 31) == 0) atomicAdd(&red[r], v);
    }
    __syncthreads();
    if (tid < RANK) g_u[t * RANK + tid] = red[tid] * SCALINGF;
}

// ------------------------------------------------------------------ main
extern __shared__ char dynsmem[];

__global__ __launch_bounds__(THREADS, 2)
void lora4bit_hmma_kernel(const int* __restrict__ q,
                          const float* __restrict__ absmax,
                          const float* __restrict__ lora_B,
                          float* __restrict__ out) {
    __shared__ float lut[16];
    __shared__ float Us[BM * RANK];   // u for this CTA's 128 token rows
    __shared__ float Bs[BN * RANK];   // lora_B for this CTA's 64 out rows

    const int tid  = threadIdx.x;
    const int wid  = tid >> 5;
    const int lane = tid & 31;
    const int bn = blockIdx.x * BN;
    const int bm = blockIdx.y * BM;

    // 1024-aligned dynamic smem base
    const uint32_t dbase = (smem_u32(dynsmem) + 1023u) & ~1023u;
    char* dptr = dynsmem + (dbase - smem_u32(dynsmem));

    if (tid < 16) lut[tid] = c_nf4[tid];
    // Us: 2048 floats = 512 float4
    {
        const float4* src = (const float4*)(g_u + (size_t)bm * RANK);
#pragma unroll
        for (int k = 0; k < 4; ++k)
            ((float4*)Us)[tid + k * 128] = src[tid + k * 128];
    }
    // Bs: 1024 floats = 256 float4
    {
        const float4* src = (const float4*)(lora_B + (size_t)bn * RANK);
#pragma unroll
        for (int k = 0; k < 2; ++k)
            ((float4*)Bs)[tid + k * 128] = src[tid + k * 128];
    }

    // ---- producer index mapping
    const int nrow  = tid >> 1;           // W tile row (n), 0..63
    const int khalf = (tid & 1) * 32;     // 32 codes each
    const int xrow  = tid >> 3;           // x rows 0..15 (+16*g)
    const int xch   = tid & 7;            // 16B chunk in 128B row

    const int*   qptr  = q + (size_t)(bn + nrow) * IN_F + khalf;
    const float* amptr = absmax + (size_t)(bn + nrow) * (IN_F / 64);

    // ---- prologue: codes/scale for it=0, cp.async x stage 0
    int4 qreg[8];
    {
        const int4* p = (const int4*)qptr;
#pragma unroll
        for (int v = 0; v < 8; ++v) qreg[v] = p[v];
    }
    float scale_cur = amptr[0];

    {
        uint32_t st = dbase;  // stage 0
#pragma unroll
        for (int g = 0; g < 8; ++g) {
            int row = xrow + g * 16;
            uint32_t off = sw128((uint32_t)(row * 128 + xch * 16));
            cp16(st + XHI_OFF + off, g_xhi + (size_t)(bm + row) * IN_F + xch * 8);
            cp16(st + XLO_OFF + off, g_xlo + (size_t)(bm + row) * IN_F + xch * 8);
        }
        cp_commit();
    }
    __syncthreads();   // lut/Us/Bs visible

    // ---- mma lane mapping
    const int wm = (wid & 1) * 64;
    const int wn = (wid >> 1) * 32;
    const int am_r = (lane & 7) + ((lane >> 3) & 1) * 8;
    const int a_kb = (lane >> 4) * 16;
    const int b_nr = (lane & 7) + ((lane >> 4) & 1) * 8;
    const int b_kb = ((lane >> 3) & 1) * 16;

    float acc[4][4][4];
#pragma unroll
    for (int i = 0; i < 4; ++i)
#pragma unroll
        for (int j = 0; j < 4; ++j)
#pragma unroll
            for (int e = 0; e < 4; ++e) acc[i][j][e] = 0.0f;

    for (int it = 0; it < K_ITERS; ++it) {
        const int s = it & 1;
        const uint32_t stg = dbase + s * STAGE_BYTES;
        char* stgp = dptr + s * STAGE_BYTES;

        cp_wait0();   // x tiles of stage s arrived

        // ---- dequant W chunk (codes in qreg) into stage s
        {
            float s0 = scale_cur;
#pragma unroll
            for (int g = 0; g < 4; ++g) {
                union { __nv_bfloat16 h[8]; uint4 v; } hib, lob;
#pragma unroll
                for (int p = 0; p < 2; ++p) {
                    int4 qq = qreg[g * 2 + p];
                    int cs[4] = {qq.x, qq.y, qq.z, qq.w};
#pragma unroll
                    for (int j = 0; j < 4; ++j) {
                        float w = lut[cs[j] & 15] * s0;
                        __nv_bfloat16 h = __float2bfloat16(w);
                        hib.h[p * 4 + j] = h;
                        lob.h[p * 4 + j] =
                            __float2bfloat16(w - __bfloat162float(h));
                    }
                }
                uint32_t off =
                    sw128((uint32_t)(nrow * 128 + khalf * 2 + g * 16));
                *(uint4*)(stgp + WHI_OFF + off) = hib.v;
                *(uint4*)(stgp + WLO_OFF + off) = lob.v;
            }
        }
        __syncthreads();   // W writes visible; stage s^1 consumers done

        // ---- prefetch next chunk: codes->regs, x->stage s^1
        if (it + 1 < K_ITERS) {
            const int4* p = (const int4*)(qptr + (it + 1) * BK);
#pragma unroll
            for (int v = 0; v < 8; ++v) qreg[v] = p[v];
            scale_cur = amptr[it + 1];

            uint32_t st = dbase + (s ^ 1) * STAGE_BYTES;
            const int kk = (it + 1) * BK + xch * 8;
#pragma unroll
            for (int g = 0; g < 8; ++g) {
                int row = xrow + g * 16;
                uint32_t off = sw128((uint32_t)(row * 128 + xch * 16));
                cp16(st + XHI_OFF + off,
                     g_xhi + (size_t)(bm + row) * IN_F + kk);
                cp16(st + XLO_OFF + off,
                     g_xlo + (size_t)(bm + row) * IN_F + kk);
            }
            cp_commit();
        }

        // ---- compute on stage s
#pragma unroll
        for (int ks = 0; ks < 4; ++ks) {
            uint32_t ah[4][4], al[4][4];
#pragma unroll
            for (int mi = 0; mi < 4; ++mi) {
                uint32_t off = sw128(
                    (uint32_t)((wm + mi * 16 + am_r) * 128 + ks * 32 + a_kb));
                ldsm4(ah[mi], stg + XHI_OFF + off);
                ldsm4(al[mi], stg + XLO_OFF + off);
            }
            uint32_t bh[4][2], bl[4][2];
#pragma unroll
            for (int jp = 0; jp < 2; ++jp) {
                uint32_t off = sw128(
                    (uint32_t)((wn + jp * 16 + b_nr) * 128 + ks * 32 + b_kb));
                uint32_t t[4];
                ldsm4(t, stg + WHI_OFF + off);
                bh[jp * 2][0] = t[0]; bh[jp * 2][1] = t[1];
                bh[jp * 2 + 1][0] = t[2]; bh[jp * 2 + 1][1] = t[3];
                ldsm4(t, stg + WLO_OFF + off);
                bl[jp * 2][0] = t[0]; bl[jp * 2][1] = t[1];
                bl[jp * 2 + 1][0] = t[2]; bl[jp * 2 + 1][1] = t[3];
            }
#pragma unroll
            for (int mi = 0; mi < 4; ++mi)
#pragma unroll
                for (int nj = 0; nj < 4; ++nj) {
                    mma16816(acc[mi][nj], ah[mi], bh[nj]);
                    mma16816(acc[mi][nj], al[mi], bh[nj]);
                    mma16816(acc[mi][nj], ah[mi], bl[nj]);
                }
        }
    }

    // ---- epilogue: LoRA add + store
#pragma unroll
    for (int mi = 0; mi < 4; ++mi) {
        const int rloc0 = wm + mi * 16 + (lane >> 2);
        const int rloc1 = rloc0 + 8;
        const float* u0 = Us + rloc0 * RANK;
        const float* u1 = Us + rloc1 * RANK;
#pragma unroll
        for (int nj = 0; nj < 4; ++nj) {
            const int c0 = wn + nj * 8 + (lane & 3) * 2;
            const float* bc0 = Bs + c0 * RANK;
            const float* bc1 = bc0 + RANK;
            float2 v0, v1;
            v0.x = acc[mi][nj][0] + dot16(u0, bc0);
            v0.y = acc[mi][nj][1] + dot16(u0, bc1);
            v1.x = acc[mi][nj][2] + dot16(u1, bc0);
            v1.y = acc[mi][nj][3] + dot16(u1, bc1);
            *(float2*)(out + (size_t)(bm + rloc0) * OUT_F + bn + c0) = v0;
            *(float2*)(out + (size_t)(bm + rloc1) * OUT_F + bn + c0) = v1;
        }
    }
}

// ------------------------------------------------------------------ launch
extern "C" void kernel_launch(void* const* d_in, const int* in_sizes, int n_in,
                              void* d_out, int out_size) {
    const float* x      = (const float*)d_in[0];
    const int*   q      = (const int*)  d_in[1];
    const float* absmax = (const float*)d_in[2];
    const float* lora_A = (const float*)d_in[3];
    const float* lora_B = (const float*)d_in[4];
    float* out = (float*)d_out;

    cudaFuncSetAttribute(lora4bit_hmma_kernel,
                         cudaFuncAttributeMaxDynamicSharedMemorySize, SMEM_DYN);

    prep_kernel<<<TOKENS, 256>>>(x, lora_A);

    dim3 grid(OUT_F / BN, TOKENS / BM);   // (172, 2)
    lora4bit_hmma_kernel<<<grid, THREADS, SMEM_DYN>>>(q, absmax, lora_B, out);
}